// round 10
// baseline (speedup 1.0000x reference)
#include <cuda_runtime.h>
#include <cuda_bf16.h>
#include <cstdint>

#define NPIX 12544          // 112*112 = 98*128
#define NCH  768
#define NCHUNK (NCH / 32)   // 24 channel chunks for partial norms
#define EPSF 1e-8f

// ---- GEMM tile config (legacy mma.sync; tcgen05 not reachable on compute_103) ----
#define BM 128
#define BN 128
#define BK 64
#define KT (NCH / BK)       // 12 k-tiles; 12 % 3 == 0 -> stage ring continuous
#define NSTAGES 3
#define PAD 72              // 64 + 8 bf16 elems per row (144B pitch, conflict-free)
#define NTILE_I (NPIX / BM) // 98
#define NTILE_J (NPIX / BN) // 98
#define NT (NTILE_I * NTILE_J)   // 9604
#define GRID 304            // 2 CTAs x 152 SMs, persistent

#define A_STAGE_ELE (BM * PAD)
#define B_STAGE_ELE (BN * PAD)
#define STAGE_ELE   (A_STAGE_ELE + B_STAGE_ELE)
#define STAGE_BYTES (STAGE_ELE * 2)                  // 36864
#define SMEM_TOTAL  (NSTAGES * STAGE_BYTES)          // 110592 -> 2 CTAs/SM

#define ROWGRP_SRC (32 * NCH * 2)                    // 49152 B: +32 rows in gmem
#define ROWGRP_DST (32 * PAD * 2)                    // 4608  B: +32 rows in smem

// ---------------- scratch (no allocations allowed) ----------------
__device__ __nv_bfloat16 g_Xt[(size_t)NPIX * NCH];   // [pixel][channel] bf16
__device__ __nv_bfloat16 g_St[(size_t)NPIX * NCH];
__device__ float g_partx[NCHUNK * NPIX];             // per-chunk partial sum x^2
__device__ float g_parts[NCHUNK * NPIX];
__device__ float g_sx[NPIX];
__device__ float g_ss[NPIX];
__device__ float g_inv_bn[NPIX];
__device__ unsigned long long g_best[NPIX];
__device__ float g_loss[NPIX];

// ------- transpose + fp32->bf16 + deterministic partial norms -------
__global__ void k_transpose(const float* __restrict__ src, int dst_sel) {
    __shared__ float tile[32][33];
    __nv_bfloat16* dst = dst_sel ? g_St : g_Xt;
    float* part = dst_sel ? g_parts : g_partx;
    int i0 = blockIdx.x * 32;
    int c0 = blockIdx.y * 32;
    tile[threadIdx.y][threadIdx.x] =
        src[(size_t)(c0 + threadIdx.y) * NPIX + i0 + threadIdx.x];
    __syncthreads();
    float v = tile[threadIdx.x][threadIdx.y];   // channel c0+tx, pixel i0+ty
    dst[(size_t)(i0 + threadIdx.y) * NCH + c0 + threadIdx.x] = __float2bfloat16(v);
    float sq = v * v;
    #pragma unroll
    for (int o = 16; o > 0; o >>= 1)
        sq += __shfl_xor_sync(0xffffffffu, sq, o);
    if (threadIdx.x == 0)
        part[(size_t)blockIdx.y * NPIX + i0 + threadIdx.y] = sq;  // unique writer
}

// ---------------- finish norms (deterministic sum of 24 partials) ----------------
__global__ void k_finish() {
    int i = blockIdx.x * 256 + threadIdx.x;
    if (i >= NPIX) return;
    float sx = 0.f, ss = 0.f;
    #pragma unroll
    for (int c = 0; c < NCHUNK; c++) {
        sx += g_partx[c * NPIX + i];
        ss += g_parts[c * NPIX + i];
    }
    g_sx[i] = sx;
    g_ss[i] = ss;
    g_inv_bn[i] = 1.0f / (sqrtf(ss + EPSF) + EPSF);
    g_best[i] = 0ull;
}

// ---- strength-reduced stage loader: 8 cp.async w/ constant-stride offsets ----
__device__ __forceinline__ void load_stage(uint32_t a_dst, uint32_t b_dst,
                                           const char* a_src, const char* b_src) {
    #pragma unroll
    for (int u = 0; u < 4; u++) {
        asm volatile("cp.async.cg.shared.global [%0], [%1], 16;"
                     :: "r"(a_dst + u * ROWGRP_DST), "l"(a_src + u * ROWGRP_SRC));
        asm volatile("cp.async.cg.shared.global [%0], [%1], 16;"
                     :: "r"(b_dst + u * ROWGRP_DST), "l"(b_src + u * ROWGRP_SRC));
    }
    asm volatile("cp.async.commit_group;" ::: "memory");
}

// -------- persistent GEMM (mma.sync bf16) + fused per-row argmax --------
__global__ void __launch_bounds__(256, 2) k_gemm_argmax() {
    extern __shared__ char smem[];

    const int t = threadIdx.x, lane = t & 31, warp = t >> 5;
    const int wm = warp >> 2;          // 0..1  -> 64-row slice
    const int wn = warp & 3;           // 0..3  -> 32-col slice

    // loader lattice: row = (t>>3)+32u, sub = t&7
    const int lrow = t >> 3, lsub = t & 7;
    const uint32_t smem_base = (uint32_t)__cvta_generic_to_shared(smem);
    const uint32_t a_dst0 = smem_base + (lrow * PAD) * 2 + lsub * 16;
    const uint32_t b_dst0 = a_dst0 + A_STAGE_ELE * 2;

    // ldmatrix per-warp byte offsets (relative to stage base)
    const int a_lrow = lane & 15;
    const int a_lcol = (lane >> 4) << 3;
    const int b_lrow = lane & 7;
    const int b_tile = (lane >> 4) & 1;
    const int b_lcol = ((lane >> 3) & 1) << 3;
    uint32_t a_off[4], b_off[2];
    #pragma unroll
    for (int mt = 0; mt < 4; mt++)
        a_off[mt] = ((wm * 64 + mt * 16 + a_lrow) * PAD + a_lcol) * 2;
    #pragma unroll
    for (int np = 0; np < 2; np++)
        b_off[np] = (A_STAGE_ELE +
                     (wn * 32 + np * 16 + b_tile * 8 + b_lrow) * PAD + b_lcol) * 2;

    // prologue: fill stages 0,1 of first tile
    {
        int g0 = blockIdx.x;
        int i0 = (g0 / NTILE_J) * BM, j0 = (g0 % NTILE_J) * BN;
        const char* a_src = (const char*)&g_Xt[(size_t)(i0 + lrow) * NCH] + lsub * 16;
        const char* b_src = (const char*)&g_St[(size_t)(j0 + lrow) * NCH] + lsub * 16;
        load_stage(a_dst0, b_dst0, a_src, b_src);
        load_stage(a_dst0 + STAGE_BYTES, b_dst0 + STAGE_BYTES,
                   a_src + BK * 2, b_src + BK * 2);
    }

    #pragma unroll 1
    for (int g = blockIdx.x; g < NT; g += GRID) {
        const int i0 = (g / NTILE_J) * BM, j0 = (g % NTILE_J) * BN;
        const int gn = (g + GRID < NT) ? (g + GRID) : (int)blockIdx.x; // wrapped dummy
        const int i0n = (gn / NTILE_J) * BM, j0n = (gn % NTILE_J) * BN;
        const char* a_srcC = (const char*)&g_Xt[(size_t)(i0 + lrow) * NCH] + lsub * 16;
        const char* b_srcC = (const char*)&g_St[(size_t)(j0 + lrow) * NCH] + lsub * 16;
        const char* a_srcN = (const char*)&g_Xt[(size_t)(i0n + lrow) * NCH] + lsub * 16;
        const char* b_srcN = (const char*)&g_St[(size_t)(j0n + lrow) * NCH] + lsub * 16;

        float acc[4][4][4];
        #pragma unroll
        for (int a = 0; a < 4; a++)
            #pragma unroll
            for (int b = 0; b < 4; b++)
                #pragma unroll
                for (int e = 0; e < 4; e++) acc[a][b][e] = 0.f;

        #pragma unroll
        for (int kt = 0; kt < KT; kt++) {
            // invariant: pending groups = {kt, kt+1}; wait 1 -> group kt done
            asm volatile("cp.async.wait_group 1;" ::: "memory");
            __syncthreads();
            {   // lookahead load (crosses tile boundary; ring stays kt%3)
                const int kl = kt + 2;
                const int st = kl % NSTAGES;
                if (kl < KT)
                    load_stage(a_dst0 + st * STAGE_BYTES, b_dst0 + st * STAGE_BYTES,
                               a_srcC + kl * (BK * 2), b_srcC + kl * (BK * 2));
                else
                    load_stage(a_dst0 + st * STAGE_BYTES, b_dst0 + st * STAGE_BYTES,
                               a_srcN + (kl - KT) * (BK * 2),
                               b_srcN + (kl - KT) * (BK * 2));
            }

            const uint32_t stage_base = smem_base + (kt % NSTAGES) * STAGE_BYTES;

            #pragma unroll
            for (int kk = 0; kk < 4; kk++) {
                const uint32_t koff = kk * 32;   // 16 bf16 = 32 bytes per kk step
                uint32_t af[4][4];
                #pragma unroll
                for (int mt = 0; mt < 4; mt++)
                    asm volatile(
                        "ldmatrix.sync.aligned.m8n8.x4.shared.b16 {%0,%1,%2,%3}, [%4];"
                        : "=r"(af[mt][0]), "=r"(af[mt][1]),
                          "=r"(af[mt][2]), "=r"(af[mt][3])
                        : "r"(stage_base + a_off[mt] + koff));
                uint32_t bf[4][2];
                #pragma unroll
                for (int np = 0; np < 2; np++)
                    asm volatile(
                        "ldmatrix.sync.aligned.m8n8.x4.shared.b16 {%0,%1,%2,%3}, [%4];"
                        : "=r"(bf[np * 2][0]), "=r"(bf[np * 2][1]),
                          "=r"(bf[np * 2 + 1][0]), "=r"(bf[np * 2 + 1][1])
                        : "r"(stage_base + b_off[np] + koff));
                #pragma unroll
                for (int mt = 0; mt < 4; mt++)
                    #pragma unroll
                    for (int nt = 0; nt < 4; nt++)
                        asm volatile(
                            "mma.sync.aligned.m16n8k16.row.col.f32.bf16.bf16.f32 "
                            "{%0,%1,%2,%3}, {%4,%5,%6,%7}, {%8,%9}, {%0,%1,%2,%3};"
                            : "+f"(acc[mt][nt][0]), "+f"(acc[mt][nt][1]),
                              "+f"(acc[mt][nt][2]), "+f"(acc[mt][nt][3])
                            : "r"(af[mt][0]), "r"(af[mt][1]),
                              "r"(af[mt][2]), "r"(af[mt][3]),
                              "r"(bf[nt][0]), "r"(bf[nt][1]));
            }
        }

        // ---- epilogue (no smem, no sync; overlaps in-flight next-tile loads) ----
        #pragma unroll
        for (int mt = 0; mt < 4; mt++) {
            #pragma unroll
            for (int rh = 0; rh < 2; rh++) {
                int row = i0 + wm * 64 + mt * 16 + rh * 8 + (lane >> 2);
                float bv = -3.4e38f;
                int   bj = 0;
                #pragma unroll
                for (int nt = 0; nt < 4; nt++) {
                    #pragma unroll
                    for (int e = 0; e < 2; e++) {
                        int cl = wn * 32 + nt * 8 + (lane & 3) * 2 + e;
                        float v = acc[mt][nt][rh * 2 + e] * __ldg(&g_inv_bn[j0 + cl]);
                        if (v > bv) { bv = v; bj = j0 + cl; }  // ascending j ties
                    }
                }
                #pragma unroll
                for (int o = 1; o < 4; o <<= 1) {
                    float ov = __shfl_xor_sync(0xffffffffu, bv, o);
                    int   oj = __shfl_xor_sync(0xffffffffu, bj, o);
                    if (ov > bv || (ov == bv && oj < bj)) { bv = ov; bj = oj; }
                }
                if ((lane & 3) == 0) {
                    unsigned int u = __float_as_uint(bv);
                    u = (u & 0x80000000u) ? ~u : (u | 0x80000000u);
                    unsigned long long p =
                        ((unsigned long long)u << 32) | (unsigned int)(~(unsigned)bj);
                    atomicMax(&g_best[row], p);
                }
            }
        }
    }
}

// ---------------- cos loss: warp per pixel, bf16 rows, fp32 accum ----------------
__global__ void k_cos() {
    int gw = (blockIdx.x * 256 + threadIdx.x) >> 5;
    int lane = threadIdx.x & 31;
    if (gw >= NPIX) return;
    unsigned long long p = g_best[gw];
    int j = (int)(~(unsigned int)(p & 0xFFFFFFFFull));

    const uint4* xr = (const uint4*)&g_Xt[(size_t)gw * NCH];
    const uint4* sr = (const uint4*)&g_St[(size_t)j * NCH];
    float dot = 0.f;
    #pragma unroll
    for (int u = lane; u < 96; u += 32) {
        uint4 a = xr[u], b = sr[u];
        const __nv_bfloat162* ah = (const __nv_bfloat162*)&a;
        const __nv_bfloat162* bh = (const __nv_bfloat162*)&b;
        #pragma unroll
        for (int q = 0; q < 4; q++) {
            float2 fa = __bfloat1622float2(ah[q]);
            float2 fb = __bfloat1622float2(bh[q]);
            dot += fa.x * fb.x + fa.y * fb.y;
        }
    }
    #pragma unroll
    for (int o = 16; o > 0; o >>= 1)
        dot += __shfl_xor_sync(0xffffffffu, dot, o);
    if (lane == 0) {
        float cs = dot / ((sqrtf(g_sx[gw]) + EPSF) * (sqrtf(g_ss[j]) + EPSF));
        g_loss[gw] = 1.0f - cs;
    }
}

// ---------------- deterministic final reduction ----------------
__global__ void k_reduce(float* __restrict__ out) {
    __shared__ float sm[256];
    float sum = 0.f;
    for (int i = threadIdx.x; i < NPIX; i += 256) sum += g_loss[i];
    sm[threadIdx.x] = sum;
    __syncthreads();
    for (int o = 128; o > 0; o >>= 1) {
        if (threadIdx.x < o) sm[threadIdx.x] += sm[threadIdx.x + o];
        __syncthreads();
    }
    if (threadIdx.x == 0) out[0] = sm[0] / (float)NPIX;
}

// ---------------- launch ----------------
extern "C" void kernel_launch(void* const* d_in, const int* in_sizes, int n_in,
                              void* d_out, int out_size) {
    const float* x = (const float*)d_in[0];
    const float* s = (const float*)d_in[1];
    float* out = (float*)d_out;

    cudaFuncSetAttribute(k_gemm_argmax,
                         cudaFuncAttributeMaxDynamicSharedMemorySize, SMEM_TOTAL);

    dim3 tb(32, 32);
    dim3 tg(NPIX / 32, NCH / 32);
    k_transpose<<<tg, tb>>>(x, 0);
    k_transpose<<<tg, tb>>>(s, 1);
    k_finish<<<NPIX / 256, 256>>>();
    k_gemm_argmax<<<GRID, 256, SMEM_TOTAL>>>();
    k_cos<<<(NPIX * 32 + 255) / 256, 256>>>();
    k_reduce<<<1, 256>>>(out);
}

// round 11
// speedup vs baseline: 1.1462x; 1.1462x over previous
#include <cuda_runtime.h>
#include <cuda_bf16.h>
#include <cstdint>

#define NPIX 12544          // 112*112 = 98*128 = 49*256
#define NCH  768
#define NCHUNK (NCH / 32)   // 24 channel chunks for partial norms
#define EPSF 1e-8f

// ---- GEMM tile config (legacy mma.sync; tcgen05 not reachable on compute_103) ----
#define BM 128
#define BN 128
#define BK 64
#define KT (NCH / BK)       // 12 k-tiles
#define NSTAGES 3
#define PAD 72              // 64 + 8 bf16 elems per row (144B pitch, conflict-free)

#define A_STAGE_ELE (BM * PAD)
#define B_STAGE_ELE (BN * PAD)
#define STAGE_ELE   (A_STAGE_ELE + B_STAGE_ELE)
#define STAGE_BYTES (STAGE_ELE * 2)                  // 36864
#define SMEM_TOTAL  (NSTAGES * STAGE_BYTES)          // 110592 -> 2 CTAs/SM

#define ROWGRP_SRC (32 * NCH * 2)                    // 49152 B: +32 rows in gmem
#define ROWGRP_DST (32 * PAD * 2)                    // 4608  B: +32 rows in smem

// ---------------- scratch (no allocations allowed) ----------------
__device__ __nv_bfloat16 g_Xt[(size_t)NPIX * NCH];   // [pixel][channel] bf16
__device__ __nv_bfloat16 g_St[(size_t)NPIX * NCH];
__device__ float g_partx[NCHUNK * NPIX];             // per-chunk partial sum x^2
__device__ float g_parts[NCHUNK * NPIX];
__device__ float g_sx[NPIX];
__device__ float g_ss[NPIX];
__device__ float g_inv_bn[NPIX];
__device__ unsigned long long g_best[NPIX];
__device__ float g_loss[NPIX];

// ------- fused transpose (x & s) + fp32->bf16 + partial norms, vectorized -------
// block: 256 thr; tile: 32 channels x 256 pixels; grid (49, 24, 2)
__global__ void k_transpose(const float* __restrict__ xsrc,
                            const float* __restrict__ ssrc) {
    __shared__ float sm[32][257];    // pad 1 -> conflict-free column reads
    const float* src = blockIdx.z ? ssrc : xsrc;
    __nv_bfloat16* dst = blockIdx.z ? g_St : g_Xt;
    float* part = blockIdx.z ? g_parts : g_partx;
    const int i0 = blockIdx.x * 256;
    const int c0 = blockIdx.y * 32;
    const int t = threadIdx.x;

    // read: 32 rows x 64 float4 = 2048 float4, 8 per thread, coalesced
    #pragma unroll
    for (int u = 0; u < 8; u++) {
        int idx = t + u * 256;               // 0..2047
        int c  = idx >> 6;                   // 0..31
        int p4 = idx & 63;                   // float4 index within row
        float4 v = *(const float4*)&src[(size_t)(c0 + c) * NPIX + i0 + p4 * 4];
        sm[c][p4 * 4 + 0] = v.x;
        sm[c][p4 * 4 + 1] = v.y;
        sm[c][p4 * 4 + 2] = v.z;
        sm[c][p4 * 4 + 3] = v.w;
    }
    __syncthreads();

    // write: thread t owns pixel i0+t -> 32 channels = 4 uint4, + local norm partial
    float sq = 0.f;
    uint32_t out[16];
    #pragma unroll
    for (int c = 0; c < 32; c += 2) {
        float a = sm[c][t], b = sm[c + 1][t];
        sq += a * a + b * b;
        __nv_bfloat162 h = __float22bfloat162_rn(make_float2(a, b));
        out[c >> 1] = *(uint32_t*)&h;
    }
    uint4* drow = (uint4*)&dst[(size_t)(i0 + t) * NCH + c0];
    #pragma unroll
    for (int q = 0; q < 4; q++)
        drow[q] = make_uint4(out[q * 4], out[q * 4 + 1],
                             out[q * 4 + 2], out[q * 4 + 3]);
    part[(size_t)blockIdx.y * NPIX + i0 + t] = sq;   // unique writer, coalesced
}

// ---------------- finish norms (deterministic sum of 24 partials) ----------------
__global__ void k_finish() {
    int i = blockIdx.x * 256 + threadIdx.x;
    if (i >= NPIX) return;
    float sx = 0.f, ss = 0.f;
    #pragma unroll
    for (int c = 0; c < NCHUNK; c++) {
        sx += g_partx[c * NPIX + i];
        ss += g_parts[c * NPIX + i];
    }
    g_sx[i] = sx;
    g_ss[i] = ss;
    g_inv_bn[i] = 1.0f / (sqrtf(ss + EPSF) + EPSF);
    g_best[i] = 0ull;
}

// ---- strength-reduced stage loader: 8 cp.async w/ constant-stride offsets ----
__device__ __forceinline__ void load_stage(uint32_t a_dst, uint32_t b_dst,
                                           const char* a_src, const char* b_src) {
    #pragma unroll
    for (int u = 0; u < 4; u++) {
        asm volatile("cp.async.cg.shared.global [%0], [%1], 16;"
                     :: "r"(a_dst + u * ROWGRP_DST), "l"(a_src + u * ROWGRP_SRC));
        asm volatile("cp.async.cg.shared.global [%0], [%1], 16;"
                     :: "r"(b_dst + u * ROWGRP_DST), "l"(b_src + u * ROWGRP_SRC));
    }
    asm volatile("cp.async.commit_group;" ::: "memory");
}

// ---------------- GEMM (mma.sync bf16) + fused per-row argmax ----------------
__global__ void __launch_bounds__(256, 2) k_gemm_argmax() {
    extern __shared__ char smem[];
    __shared__ float s_inv[BN];

    const int t = threadIdx.x, lane = t & 31, warp = t >> 5;
    const int wm = warp >> 2;          // 0..1  -> 64-row slice
    const int wn = warp & 3;           // 0..3  -> 32-col slice
    const int i0 = blockIdx.y * BM;
    const int j0 = blockIdx.x * BN;

    if (t < BN) s_inv[t] = g_inv_bn[j0 + t];

    float acc[4][4][4];
    #pragma unroll
    for (int a = 0; a < 4; a++)
        #pragma unroll
        for (int b = 0; b < 4; b++)
            #pragma unroll
            for (int e = 0; e < 4; e++) acc[a][b][e] = 0.f;

    // loader lattice: row = (t>>3)+32u, sub = t&7
    const int lrow = t >> 3, lsub = t & 7;
    const char* a_src = (const char*)&g_Xt[(size_t)(i0 + lrow) * NCH] + lsub * 16;
    const char* b_src = (const char*)&g_St[(size_t)(j0 + lrow) * NCH] + lsub * 16;
    const uint32_t smem_base = (uint32_t)__cvta_generic_to_shared(smem);
    const uint32_t a_dst0 = smem_base + (lrow * PAD) * 2 + lsub * 16;
    const uint32_t b_dst0 = a_dst0 + A_STAGE_ELE * 2;

    // ldmatrix per-warp byte offsets (relative to stage base)
    const int a_lrow = lane & 15;
    const int a_lcol = (lane >> 4) << 3;
    const int b_lrow = lane & 7;
    const int b_tile = (lane >> 4) & 1;
    const int b_lcol = ((lane >> 3) & 1) << 3;
    uint32_t a_off[4], b_off[2];
    #pragma unroll
    for (int mt = 0; mt < 4; mt++)
        a_off[mt] = ((wm * 64 + mt * 16 + a_lrow) * PAD + a_lcol) * 2;
    #pragma unroll
    for (int np = 0; np < 2; np++)
        b_off[np] = (A_STAGE_ELE +
                     (wn * 32 + np * 16 + b_tile * 8 + b_lrow) * PAD + b_lcol) * 2;

    load_stage(a_dst0, b_dst0, a_src, b_src);
    load_stage(a_dst0 + STAGE_BYTES, b_dst0 + STAGE_BYTES,
               a_src + BK * 2, b_src + BK * 2);

    // mainloop fully unrolled: stage bases & load offsets are immediates
    #pragma unroll
    for (int kt = 0; kt < KT; kt++) {
        if (kt < KT - 1) asm volatile("cp.async.wait_group 1;" ::: "memory");
        else             asm volatile("cp.async.wait_group 0;" ::: "memory");
        __syncthreads();
        if (kt + 2 < KT) {
            const int st = (kt + 2) % NSTAGES;
            load_stage(a_dst0 + st * STAGE_BYTES, b_dst0 + st * STAGE_BYTES,
                       a_src + (kt + 2) * (BK * 2), b_src + (kt + 2) * (BK * 2));
        }

        const uint32_t stage_base = smem_base + (kt % NSTAGES) * STAGE_BYTES;

        #pragma unroll
        for (int kk = 0; kk < 4; kk++) {
            const uint32_t koff = kk * 32;       // 16 bf16 = 32 bytes per kk step
            uint32_t af[4][4];
            #pragma unroll
            for (int mt = 0; mt < 4; mt++)
                asm volatile(
                    "ldmatrix.sync.aligned.m8n8.x4.shared.b16 {%0,%1,%2,%3}, [%4];"
                    : "=r"(af[mt][0]), "=r"(af[mt][1]), "=r"(af[mt][2]), "=r"(af[mt][3])
                    : "r"(stage_base + a_off[mt] + koff));
            uint32_t bf[4][2];
            #pragma unroll
            for (int np = 0; np < 2; np++)
                asm volatile(
                    "ldmatrix.sync.aligned.m8n8.x4.shared.b16 {%0,%1,%2,%3}, [%4];"
                    : "=r"(bf[np * 2][0]), "=r"(bf[np * 2][1]),
                      "=r"(bf[np * 2 + 1][0]), "=r"(bf[np * 2 + 1][1])
                    : "r"(stage_base + b_off[np] + koff));
            #pragma unroll
            for (int mt = 0; mt < 4; mt++)
                #pragma unroll
                for (int nt = 0; nt < 4; nt++)
                    asm volatile(
                        "mma.sync.aligned.m16n8k16.row.col.f32.bf16.bf16.f32 "
                        "{%0,%1,%2,%3}, {%4,%5,%6,%7}, {%8,%9}, {%0,%1,%2,%3};"
                        : "+f"(acc[mt][nt][0]), "+f"(acc[mt][nt][1]),
                          "+f"(acc[mt][nt][2]), "+f"(acc[mt][nt][3])
                        : "r"(af[mt][0]), "r"(af[mt][1]), "r"(af[mt][2]), "r"(af[mt][3]),
                          "r"(bf[nt][0]), "r"(bf[nt][1]));
        }
    }

    // ---- epilogue: scale by inv_bn[j], per-row argmax, atomic merge ----
    #pragma unroll
    for (int mt = 0; mt < 4; mt++) {
        #pragma unroll
        for (int rh = 0; rh < 2; rh++) {
            int row = i0 + wm * 64 + mt * 16 + rh * 8 + (lane >> 2);
            float bv = -3.4e38f;
            int   bj = 0;
            #pragma unroll
            for (int nt = 0; nt < 4; nt++) {
                #pragma unroll
                for (int e = 0; e < 2; e++) {
                    int cl = wn * 32 + nt * 8 + (lane & 3) * 2 + e;
                    float v = acc[mt][nt][rh * 2 + e] * s_inv[cl];
                    if (v > bv) { bv = v; bj = j0 + cl; }   // ascending j: first-min ties
                }
            }
            #pragma unroll
            for (int o = 1; o < 4; o <<= 1) {
                float ov = __shfl_xor_sync(0xffffffffu, bv, o);
                int   oj = __shfl_xor_sync(0xffffffffu, bj, o);
                if (ov > bv || (ov == bv && oj < bj)) { bv = ov; bj = oj; }
            }
            if ((lane & 3) == 0) {
                unsigned int u = __float_as_uint(bv);
                u = (u & 0x80000000u) ? ~u : (u | 0x80000000u);
                unsigned long long p =
                    ((unsigned long long)u << 32) | (unsigned int)(~(unsigned)bj);
                atomicMax(&g_best[row], p);
            }
        }
    }
}

// ---------------- cos loss: warp per pixel, bf16 rows, fp32 accum ----------------
__global__ void k_cos() {
    int gw = (blockIdx.x * 256 + threadIdx.x) >> 5;
    int lane = threadIdx.x & 31;
    if (gw >= NPIX) return;
    unsigned long long p = g_best[gw];
    int j = (int)(~(unsigned int)(p & 0xFFFFFFFFull));

    const uint4* xr = (const uint4*)&g_Xt[(size_t)gw * NCH];
    const uint4* sr = (const uint4*)&g_St[(size_t)j * NCH];
    float dot = 0.f;
    #pragma unroll
    for (int u = lane; u < 96; u += 32) {
        uint4 a = xr[u], b = sr[u];
        const __nv_bfloat162* ah = (const __nv_bfloat162*)&a;
        const __nv_bfloat162* bh = (const __nv_bfloat162*)&b;
        #pragma unroll
        for (int q = 0; q < 4; q++) {
            float2 fa = __bfloat1622float2(ah[q]);
            float2 fb = __bfloat1622float2(bh[q]);
            dot += fa.x * fb.x + fa.y * fb.y;
        }
    }
    #pragma unroll
    for (int o = 16; o > 0; o >>= 1)
        dot += __shfl_xor_sync(0xffffffffu, dot, o);
    if (lane == 0) {
        float cs = dot / ((sqrtf(g_sx[gw]) + EPSF) * (sqrtf(g_ss[j]) + EPSF));
        g_loss[gw] = 1.0f - cs;
    }
}

// ---------------- deterministic final reduction ----------------
__global__ void k_reduce(float* __restrict__ out) {
    __shared__ float sm[256];
    float sum = 0.f;
    for (int i = threadIdx.x; i < NPIX; i += 256) sum += g_loss[i];
    sm[threadIdx.x] = sum;
    __syncthreads();
    for (int o = 128; o > 0; o >>= 1) {
        if (threadIdx.x < o) sm[threadIdx.x] += sm[threadIdx.x + o];
        __syncthreads();
    }
    if (threadIdx.x == 0) out[0] = sm[0] / (float)NPIX;
}

// ---------------- launch ----------------
extern "C" void kernel_launch(void* const* d_in, const int* in_sizes, int n_in,
                              void* d_out, int out_size) {
    const float* x = (const float*)d_in[0];
    const float* s = (const float*)d_in[1];
    float* out = (float*)d_out;

    cudaFuncSetAttribute(k_gemm_argmax,
                         cudaFuncAttributeMaxDynamicSharedMemorySize, SMEM_TOTAL);

    k_transpose<<<dim3(NPIX / 256, NCH / 32, 2), 256>>>(x, s);
    k_finish<<<NPIX / 256, 256>>>();
    k_gemm_argmax<<<dim3(NPIX / BN, NPIX / BM), 256, SMEM_TOTAL>>>();
    k_cos<<<(NPIX * 32 + 255) / 256, 256>>>();
    k_reduce<<<1, 256>>>(out);
}